// round 15
// baseline (speedup 1.0000x reference)
#include <cuda_runtime.h>
#include <cuda_fp16.h>
#include <cstdint>

typedef unsigned long long u64;
typedef unsigned int       u32;

#define B_   8
#define V_   200
#define T_   128
#define NBLK (B_ * V_)          // 1600

// ---- pre-fragmented weights (written once by prep_w) ----
__device__ __align__(16) u32 gWBH[3 * 4096];
__device__ __align__(16) u32 gWOH[2048];

// ---- fused-kernel smem (bytes), 112KB -> 2 CTAs/SM ----
// [0,32768)       AFH  (overlay after p=2 mainloop: VBH @0, 16KB)
// [32768,65536)   AFL  (overlay after attention: AOH @32768, 16KB)
// [65536,81920)   QH   (Q frags hi, resident)
// [81920,98304)   QL   (Q frags lo, resident)
// [98304,114688)  BKH  (K single fp16)
#define SM_AFH  0
#define SM_AFL  32768
#define SM_VBH  0
#define SM_AOH  32768
#define SM_QH   65536
#define SM_QL   81920
#define SM_BKH  98304
#define SMEM_TOTAL 114688

// ---- helpers (fp16) ----
__device__ __forceinline__ u32 pack_h2(float a, float b) {
    __half2 h = __floats2half2_rn(a, b);
    return *(u32*)&h;
}
__device__ __forceinline__ void split2h(float a, float b, u32& hi, u32& lo) {
    hi = pack_h2(a, b);
    float ra = __half2float(__ushort_as_half((unsigned short)(hi & 0xFFFFu)));
    float rb = __half2float(__ushort_as_half((unsigned short)(hi >> 16)));
    lo = pack_h2(a - ra, b - rb);
}
__device__ __forceinline__ float ex2f(float x) {
    float y; asm("ex2.approx.f32 %0, %1;" : "=f"(y) : "f"(x)); return y;
}
__device__ __forceinline__ void mma16816h(float* c, const u32* a, const u32* b) {
    asm volatile(
        "mma.sync.aligned.m16n8k16.row.col.f32.f16.f16.f32 "
        "{%0,%1,%2,%3}, {%4,%5,%6,%7}, {%8,%9}, {%0,%1,%2,%3};"
        : "+f"(c[0]), "+f"(c[1]), "+f"(c[2]), "+f"(c[3])
        : "r"(a[0]), "r"(a[1]), "r"(a[2]), "r"(a[3]), "r"(b[0]), "r"(b[1]));
}
__device__ __forceinline__ void mma16808h(float* c, const u32* a, u32 b) {
    asm volatile(
        "mma.sync.aligned.m16n8k8.row.col.f32.f16.f16.f32 "
        "{%0,%1,%2,%3}, {%4,%5}, {%6}, {%0,%1,%2,%3};"
        : "+f"(c[0]), "+f"(c[1]), "+f"(c[2]), "+f"(c[3])
        : "r"(a[0]), "r"(a[1]), "r"(b));
}
__device__ __forceinline__ void vstoreh(char* bh, int off, float v) {
    *(__half*)(bh + off) = __float2half_rn(v);
}

extern __shared__ char smc[];

// ===========================================================================
// Kernel 0: pre-fragment weights into global fp16 tables (validated layouts)
// ===========================================================================
__global__ void prep_w(const float* __restrict__ Wq, const float* __restrict__ Wk,
                       const float* __restrict__ Wv, const float* __restrict__ Wo)
{
    const int p = blockIdx.x, tid = threadIdx.x;
    if (p < 3) {
        const float* W = (p == 0) ? Wq : (p == 1 ? Wk : Wv);
        for (int i = tid; i < 4096; i += 1024) {
            int o = i >> 6, cp = i & 63;
            float2 g = *(const float2*)(W + o * 128 + (cp << 1));
            int kg = cp >> 3;
            int lane_f = ((o & 7) << 2) + (cp & 3);
            int reg = (cp >> 2) & 1;
            int X = ((cp >> 2) & 7) << 2;
            int idx = ((((o >> 3) << 3) + kg) * 2 + reg) * 32 + (lane_f ^ X);
            gWBH[p * 4096 + idx] = pack_h2(g.x, g.y);
        }
    } else {
        for (int i = tid; i < 2048; i += 1024) {
            int o = i >> 5, cp = i & 31;
            float2 g = *(const float2*)(Wo + (o << 6) + (cp << 1));
            int kg = cp >> 3;
            int lane_f = ((o & 7) << 2) + (cp & 3);
            int reg = (cp >> 2) & 1;
            int X = ((cp >> 2) & 7) << 2;
            int idx = ((((o >> 3) << 2) + kg) * 2 + reg) * 32 + (lane_f ^ X);
            gWOH[idx] = pack_h2(g.x, g.y);
        }
    }
}

// ===========================================================================
// Fused kernel: concat + QKV proj + causal attention + out-proj + ReLU
// 256 threads, 2 CTAs/SM (112KB smem). Q frags smem-resident.
// ===========================================================================
__global__ __launch_bounds__(256, 2) void tatt_fused(
    const float* __restrict__ x,  const float* __restrict__ tem,
    const float* __restrict__ bq, const float* __restrict__ bk,
    const float* __restrict__ bv, const float* __restrict__ bo,
    float* __restrict__ out)
{
    u32* AFH = (u32*)(smc + SM_AFH);
    u32* AFL = (u32*)(smc + SM_AFL);
    u32* QH  = (u32*)(smc + SM_QH);
    u32* QL  = (u32*)(smc + SM_QL);
    u32* BKH = (u32*)(smc + SM_BKH);
    u32* VBH = (u32*)(smc + SM_VBH);
    u32* AOH = (u32*)(smc + SM_AOH);

    const int tid = threadIdx.x, lane = tid & 31, w = tid >> 5;
    const int blk = blockIdx.x, b = blk / V_, v = blk % V_;
    const int gid = lane >> 2, tig = lane & 3;

    // ---- stage concat input as A-fragments (hi/lo fp16 split) [validated idx] ----
    for (int i = tid; i < 8192; i += 256) {
        int cp = i >> 7, t = i & 127;
        int c0 = cp << 1;
        const float* src = (c0 < 64) ? x : tem;
        const float* pb = src + ((long)((b << 6) + (c0 & 63)) * V_ + v) * T_ + t;
        float g0 = pb[0];
        float g1 = pb[(long)V_ * T_];
        int tt = t >> 4, kg = cp >> 3, tin = t & 15;
        int lane_f = ((tin & 7) << 2) + (cp & 3);
        int reg = (tin >> 3) + (((cp >> 2) & 1) << 1);
        int X = (t >> 3) & 3;
        int idx = (((tt << 3) + kg) * 4 + reg) * 32 + (lane_f ^ X);
        split2h(g0, g1, AFH[idx], AFL[idx]);
    }
    __syncthreads();

    const int mt = w >> 1, nq = w & 1;        // 4 x 2 warp grid
    const float* bsrc[3] = {bq, bk, bv};

    // ---- three projections; Q: A split (2-term), K/V: A single (1-term) ----
#pragma unroll 1
    for (int p = 0; p < 3; ++p) {
        const u32* WBH = gWBH + p * 4096;

        float acc[2][4][4];
#pragma unroll
        for (int m2 = 0; m2 < 2; ++m2)
#pragma unroll
            for (int n2 = 0; n2 < 4; ++n2)
#pragma unroll
                for (int j = 0; j < 4; ++j) acc[m2][n2][j] = 0.f;

#pragma unroll
        for (int kg = 0; kg < 8; ++kg) {
            u32 Ah[2][4], Al[2][4], Bh[4][2];
#pragma unroll
            for (int m2 = 0; m2 < 2; ++m2) {
                int tt = mt * 2 + m2;
#pragma unroll
                for (int r = 0; r < 4; ++r) {
                    int X = (tt * 2 + (r & 1)) & 3;
                    int idx = ((tt * 8 + kg) * 4 + r) * 32 + (lane ^ X);
                    Ah[m2][r] = AFH[idx];
                    if (p == 0) Al[m2][r] = AFL[idx];
                }
            }
#pragma unroll
            for (int n2 = 0; n2 < 4; ++n2) {
                int ot = nq * 4 + n2;
#pragma unroll
                for (int r = 0; r < 2; ++r) {
                    int X = ((kg * 2 + r) & 7) << 2;
                    int idx = ((ot * 8 + kg) * 2 + r) * 32 + (lane ^ X);
                    Bh[n2][r] = WBH[idx];
                }
            }
#pragma unroll
            for (int m2 = 0; m2 < 2; ++m2)
#pragma unroll
                for (int n2 = 0; n2 < 4; ++n2) {
                    mma16816h(acc[m2][n2], Ah[m2], Bh[n2]);
                    if (p == 0) mma16816h(acc[m2][n2], Al[m2], Bh[n2]);
                }
        }

        if (p == 2) __syncthreads();   // all warps done reading A-frags -> V may overlay

#pragma unroll
        for (int m2 = 0; m2 < 2; ++m2)
#pragma unroll
            for (int n2 = 0; n2 < 4; ++n2) {
                int TT = mt * 2 + m2, hh = nq * 4 + n2;
                int o0 = hh * 8 + (tig << 1);
                float b0 = bsrc[p][o0], b1 = bsrc[p][o0 + 1];
                float v0 = acc[m2][n2][0] + b0, v1 = acc[m2][n2][1] + b1;
                float v2 = acc[m2][n2][2] + b0, v3 = acc[m2][n2][3] + b1;
                if (p == 0) {
                    const float SC = 0.5101344248f;    // 1/sqrt(8) * log2(e)
                    v0 *= SC; v1 *= SC; v2 *= SC; v3 *= SC;
                    u32 hi, lo;
                    split2h(v0, v1, hi, lo);
                    int i0 = ((hh * 8 + TT) * 2 + 0) * 32 + lane;
                    QH[i0] = hi; QL[i0] = lo;
                    split2h(v2, v3, hi, lo);
                    int i1 = ((hh * 8 + TT) * 2 + 1) * 32 + lane;
                    QH[i1] = hi; QL[i1] = lo;
                } else if (p == 1) {
                    BKH[(hh * 16 + TT * 2) * 32 + lane]     = pack_h2(v0, v1);
                    BKH[(hh * 16 + TT * 2 + 1) * 32 + lane] = pack_h2(v2, v3);
                } else {
                    // V single fp16, transpose scatter [validated offsets]
                    char* bh = smc + SM_VBH + hh * 2048 + TT * 256;
                    int d0 = tig << 1, d1 = d0 + 1;
                    int wo0 = d0 * 16 + ((gid >> 1) << 2) + ((gid & 1) << 1);
                    int wo1 = d1 * 16 + ((gid >> 1) << 2) + ((gid & 1) << 1);
                    vstoreh(bh, wo0, v0);
                    vstoreh(bh, wo1, v1);
                    vstoreh(bh, 128 + wo0, v2);
                    vstoreh(bh, 128 + wo1, v3);
                }
            }
    }
    __syncthreads();    // Q + K + V smem visible

    // ---- attention: warp w = head h, all mi 0..7 ----
    float oa[8][4];
    float l0[8], l1[8];
    {
        const int h = w;
        const bool m0 = (2 * tig) <= gid;
        const bool m1 = (2 * tig + 1) <= gid;

        u32 qh[8][2], ql[8][2];
#pragma unroll
        for (int mi = 0; mi < 8; ++mi) {
            qh[mi][0] = QH[((h * 8 + mi) * 2 + 0) * 32 + lane];
            qh[mi][1] = QH[((h * 8 + mi) * 2 + 1) * 32 + lane];
            ql[mi][0] = QL[((h * 8 + mi) * 2 + 0) * 32 + lane];
            ql[mi][1] = QL[((h * 8 + mi) * 2 + 1) * 32 + lane];
        }
#pragma unroll
        for (int mi = 0; mi < 8; ++mi) {
            oa[mi][0] = oa[mi][1] = oa[mi][2] = oa[mi][3] = 0.f;
            l0[mi] = l1[mi] = 0.f;
        }

#pragma unroll
        for (int kg = 0; kg < 8; ++kg) {
            u32 kh0 = BKH[(h * 16 + 2 * kg) * 32 + lane];
            u32 kh1 = BKH[(h * 16 + 2 * kg + 1) * 32 + lane];
            u32 vh[2];
            vh[0] = VBH[((h * 8 + kg) * 2 + 0) * 32 + lane];
            vh[1] = VBH[((h * 8 + kg) * 2 + 1) * 32 + lane];

#pragma unroll
            for (int mi = 0; mi < 8; ++mi) {
                if (mi < kg) continue;               // compile-time prune
                bool diag = (mi == kg);

                float s0[4] = {0.f, 0.f, 0.f, 0.f};
                float s1[4] = {0.f, 0.f, 0.f, 0.f};
                mma16808h(s0, qh[mi], kh0); mma16808h(s0, ql[mi], kh0);
                mma16808h(s1, qh[mi], kh1); mma16808h(s1, ql[mi], kh1);

                float e00 = ex2f(s0[0]), e01 = ex2f(s0[1]);
                float e02 = ex2f(s0[2]), e03 = ex2f(s0[3]);
                float e10 = ex2f(s1[0]), e11 = ex2f(s1[1]);
                float e12 = ex2f(s1[2]), e13 = ex2f(s1[3]);
                if (diag) {
                    e00 = m0 ? e00 : 0.f; e01 = m1 ? e01 : 0.f;
                    e10 = 0.f;            e11 = 0.f;
                    e12 = m0 ? e12 : 0.f; e13 = m1 ? e13 : 0.f;
                }
                l0[mi] += (e00 + e01) + (e10 + e11);
                l1[mi] += (e02 + e03) + (e12 + e13);

                // P single fp16 (no lo split)
                u32 ph[4];
                ph[0] = pack_h2(e00, e01);
                ph[1] = pack_h2(e02, e03);
                ph[2] = pack_h2(e10, e11);
                ph[3] = pack_h2(e12, e13);

                mma16816h(oa[mi], ph, vh);
            }
        }
    }
    __syncthreads();          // all warps done reading K/V regions

    // ---- normalize + write AO frags (single fp16, overlay A-lo region) ----
    {
        const int h = w;
#pragma unroll
        for (int mi = 0; mi < 8; ++mi) {
            float L0 = l0[mi], L1 = l1[mi];
            L0 += __shfl_xor_sync(0xFFFFFFFFu, L0, 1);
            L0 += __shfl_xor_sync(0xFFFFFFFFu, L0, 2);
            L1 += __shfl_xor_sync(0xFFFFFFFFu, L1, 1);
            L1 += __shfl_xor_sync(0xFFFFFFFFu, L1, 2);
            float inv0 = __fdividef(1.f, L0), inv1 = __fdividef(1.f, L1);
            float r0 = oa[mi][0] * inv0, r1 = oa[mi][1] * inv0;
            float r2 = oa[mi][2] * inv1, r3 = oa[mi][3] * inv1;

            int kga = h >> 1, regb = (h & 1) << 1;
            int X0 = (mi * 2) & 3, X1 = (mi * 2 + 1) & 3;
            int base = (mi * 4 + kga) * 4;
            AOH[(base + regb) * 32 + (lane ^ X0)]     = pack_h2(r0, r1);
            AOH[(base + regb + 1) * 32 + (lane ^ X1)] = pack_h2(r2, r3);
        }
    }
    __syncthreads();

    // ---- out projection (A single x Wo single) + bias + ReLU -> global ----
    {
        float acc[2][4][4];
#pragma unroll
        for (int m2 = 0; m2 < 2; ++m2)
#pragma unroll
            for (int n2 = 0; n2 < 4; ++n2)
#pragma unroll
                for (int j = 0; j < 4; ++j) acc[m2][n2][j] = 0.f;

#pragma unroll
        for (int kg = 0; kg < 4; ++kg) {
            u32 Ah[2][4], Bh[4][2];
#pragma unroll
            for (int m2 = 0; m2 < 2; ++m2) {
                int tt = mt * 2 + m2;
#pragma unroll
                for (int r = 0; r < 4; ++r) {
                    int X = (tt * 2 + (r & 1)) & 3;
                    int idx = ((tt * 4 + kg) * 4 + r) * 32 + (lane ^ X);
                    Ah[m2][r] = AOH[idx];
                }
            }
#pragma unroll
            for (int n2 = 0; n2 < 4; ++n2) {
                int ot = nq * 4 + n2;
#pragma unroll
                for (int r = 0; r < 2; ++r) {
                    int X = ((kg * 2 + r) & 7) << 2;
                    int idx = ((ot * 4 + kg) * 2 + r) * 32 + (lane ^ X);
                    Bh[n2][r] = gWOH[idx];
                }
            }
#pragma unroll
            for (int m2 = 0; m2 < 2; ++m2)
#pragma unroll
                for (int n2 = 0; n2 < 4; ++n2)
                    mma16816h(acc[m2][n2], Ah[m2], Bh[n2]);
        }

#pragma unroll
        for (int m2 = 0; m2 < 2; ++m2)
#pragma unroll
            for (int n2 = 0; n2 < 4; ++n2) {
                int t0 = ((mt * 2 + m2) << 4) + gid;
                int o0 = ((nq * 4 + n2) << 3) + (tig << 1);
                float b0 = bo[o0], b1 = bo[o0 + 1];
                long base0 = ((long)(b * 64 + o0) * V_ + v) * T_;
                long base1 = base0 + (long)V_ * T_;
                out[base0 + t0]     = fmaxf(acc[m2][n2][0] + b0, 0.f);
                out[base1 + t0]     = fmaxf(acc[m2][n2][1] + b1, 0.f);
                out[base0 + t0 + 8] = fmaxf(acc[m2][n2][2] + b0, 0.f);
                out[base1 + t0 + 8] = fmaxf(acc[m2][n2][3] + b1, 0.f);
            }
    }
}

// ---------------------------------------------------------------------------
extern "C" void kernel_launch(void* const* d_in, const int* in_sizes, int n_in,
                              void* d_out, int out_size)
{
    (void)in_sizes; (void)n_in; (void)out_size;
    const float* x  = (const float*)d_in[0];
    const float* te = (const float*)d_in[1];
    const float* Wq = (const float*)d_in[2];
    const float* bq = (const float*)d_in[3];
    const float* Wk = (const float*)d_in[4];
    const float* bk = (const float*)d_in[5];
    const float* Wv = (const float*)d_in[6];
    const float* bv = (const float*)d_in[7];
    const float* Wo = (const float*)d_in[8];
    const float* bo = (const float*)d_in[9];
    float* out = (float*)d_out;

    cudaFuncSetAttribute(tatt_fused, cudaFuncAttributeMaxDynamicSharedMemorySize, SMEM_TOTAL);

    prep_w<<<4, 1024>>>(Wq, Wk, Wv, Wo);
    tatt_fused<<<NBLK, 256, SMEM_TOTAL>>>(x, te, bq, bk, bv, bo, out);
}

// round 16
// speedup vs baseline: 1.1243x; 1.1243x over previous
#include <cuda_runtime.h>
#include <cuda_fp16.h>
#include <cstdint>

typedef unsigned long long u64;
typedef unsigned int       u32;

#define B_   8
#define V_   200
#define T_   128
#define NBLK (B_ * V_)          // 1600

// ---- pre-fragmented weights (written once by prep_w); reg-paired layout ----
__device__ __align__(16) u32 gWBH[3 * 4096];
__device__ __align__(16) u32 gWOH[2048];

// ---- fused-kernel smem (bytes), 112KB -> 2 CTAs/SM ----
// [0,32768)       AFH  (overlay after p=2 mainloop: VBH @0, 16KB)
// [32768,65536)   AFL  (overlay after attention: AOH @32768, 16KB)
// [65536,98304)   QHL  (Q frags hi/lo interleaved, resident)
// [98304,114688)  BKH  (K single fp16)
#define SM_AFH  0
#define SM_AFL  32768
#define SM_VBH  0
#define SM_AOH  32768
#define SM_QHL  65536
#define SM_BKH  98304
#define SMEM_TOTAL 114688

// ---- helpers (fp16) ----
__device__ __forceinline__ u32 pack_h2(float a, float b) {
    __half2 h = __floats2half2_rn(a, b);
    return *(u32*)&h;
}
__device__ __forceinline__ void split2h(float a, float b, u32& hi, u32& lo) {
    hi = pack_h2(a, b);
    float ra = __half2float(__ushort_as_half((unsigned short)(hi & 0xFFFFu)));
    float rb = __half2float(__ushort_as_half((unsigned short)(hi >> 16)));
    lo = pack_h2(a - ra, b - rb);
}
__device__ __forceinline__ float ex2f(float x) {
    float y; asm("ex2.approx.f32 %0, %1;" : "=f"(y) : "f"(x)); return y;
}
__device__ __forceinline__ void mma16816h(float* c, const u32* a, const u32* b) {
    asm volatile(
        "mma.sync.aligned.m16n8k16.row.col.f32.f16.f16.f32 "
        "{%0,%1,%2,%3}, {%4,%5,%6,%7}, {%8,%9}, {%0,%1,%2,%3};"
        : "+f"(c[0]), "+f"(c[1]), "+f"(c[2]), "+f"(c[3])
        : "r"(a[0]), "r"(a[1]), "r"(a[2]), "r"(a[3]), "r"(b[0]), "r"(b[1]));
}
__device__ __forceinline__ void vstoreh(char* bh, int off, float v) {
    *(__half*)(bh + off) = __float2half_rn(v);
}

extern __shared__ char smc[];

// ===========================================================================
// Kernel 0: pre-fragment weights into global fp16 tables.
// NEW layout: regs paired per lane (LDG.64 on consumer), no XOR swizzle.
//   WB:  idx = ((ot*8 + kg)*32 + lane_f)*2 + reg
//   WO:  idx = ((ot*4 + kg)*32 + lane_f)*2 + reg
// ===========================================================================
__global__ void prep_w(const float* __restrict__ Wq, const float* __restrict__ Wk,
                       const float* __restrict__ Wv, const float* __restrict__ Wo)
{
    const int p = blockIdx.x, tid = threadIdx.x;
    if (p < 3) {
        const float* W = (p == 0) ? Wq : (p == 1 ? Wk : Wv);
        for (int i = tid; i < 4096; i += 1024) {
            int o = i >> 6, cp = i & 63;
            float2 g = *(const float2*)(W + o * 128 + (cp << 1));
            int ot = o >> 3, kg = cp >> 3;
            int reg = (cp >> 2) & 1;
            int lane_f = ((o & 7) << 2) + (cp & 3);
            int idx = ((ot * 8 + kg) * 32 + lane_f) * 2 + reg;
            gWBH[p * 4096 + idx] = pack_h2(g.x, g.y);
        }
    } else {
        for (int i = tid; i < 2048; i += 1024) {
            int o = i >> 5, cp = i & 31;
            float2 g = *(const float2*)(Wo + (o << 6) + (cp << 1));
            int ot = o >> 3, kg = cp >> 3;
            int reg = (cp >> 2) & 1;
            int lane_f = ((o & 7) << 2) + (cp & 3);
            int idx = ((ot * 4 + kg) * 32 + lane_f) * 2 + reg;
            gWOH[idx] = pack_h2(g.x, g.y);
        }
    }
}

// ===========================================================================
// Fused kernel: concat + QKV proj + causal attention + out-proj + ReLU
// 256 threads, 2 CTAs/SM (112KB smem).
// ===========================================================================
__global__ __launch_bounds__(256, 2) void tatt_fused(
    const float* __restrict__ x,  const float* __restrict__ tem,
    const float* __restrict__ bq, const float* __restrict__ bk,
    const float* __restrict__ bv, const float* __restrict__ bo,
    float* __restrict__ out)
{
    u32* AFH = (u32*)(smc + SM_AFH);
    u32* AFL = (u32*)(smc + SM_AFL);
    u32* QHL = (u32*)(smc + SM_QHL);
    u32* BKH = (u32*)(smc + SM_BKH);
    u32* VBH = (u32*)(smc + SM_VBH);
    u32* AOH = (u32*)(smc + SM_AOH);

    const int tid = threadIdx.x, lane = tid & 31, w = tid >> 5;
    const int blk = blockIdx.x, b = blk / V_, v = blk % V_;
    const int gid = lane >> 2, tig = lane & 3;

    // ---- stage concat input as A-fragments; float4 global loads ----
    for (int i = tid; i < 2048; i += 256) {
        int cp = i >> 5;                 // channel pair 0..63
        int t0 = (i & 31) << 2;          // t quad base
        int c0 = cp << 1;
        const float* src = (c0 < 64) ? x : tem;
        const float* pb = src + ((long)((b << 6) + (c0 & 63)) * V_ + v) * T_ + t0;
        float4 ga = *(const float4*)pb;
        float4 gb = *(const float4*)(pb + (long)V_ * T_);
        float a4[4] = {ga.x, ga.y, ga.z, ga.w};
        float b4[4] = {gb.x, gb.y, gb.z, gb.w};
        int kg = cp >> 3;
#pragma unroll
        for (int k = 0; k < 4; ++k) {
            int t = t0 + k;
            int tt = t >> 4, tin = t & 15;
            int lane_f = ((tin & 7) << 2) + (cp & 3);
            int reg = (tin >> 3) + (((cp >> 2) & 1) << 1);
            int X = (t >> 3) & 3;
            int idx = (((tt << 3) + kg) * 4 + reg) * 32 + (lane_f ^ X);
            split2h(a4[k], b4[k], AFH[idx], AFL[idx]);
        }
    }
    __syncthreads();

    const int mt = w >> 1, nq = w & 1;        // 4 x 2 warp grid
    const float* bsrc[3] = {bq, bk, bv};

    // ---- three projections; Q: A split (2-term), K/V: A single (1-term) ----
#pragma unroll 1
    for (int p = 0; p < 3; ++p) {
        const u32* WBH = gWBH + p * 4096;

        float acc[2][4][4];
#pragma unroll
        for (int m2 = 0; m2 < 2; ++m2)
#pragma unroll
            for (int n2 = 0; n2 < 4; ++n2)
#pragma unroll
                for (int j = 0; j < 4; ++j) acc[m2][n2][j] = 0.f;

#pragma unroll
        for (int kg = 0; kg < 8; ++kg) {
            u32 Ah[2][4], Al[2][4], Bh[4][2];
#pragma unroll
            for (int m2 = 0; m2 < 2; ++m2) {
                int tt = mt * 2 + m2;
#pragma unroll
                for (int r = 0; r < 4; ++r) {
                    int X = (tt * 2 + (r & 1)) & 3;
                    int idx = ((tt * 8 + kg) * 4 + r) * 32 + (lane ^ X);
                    Ah[m2][r] = AFH[idx];
                    if (p == 0) Al[m2][r] = AFL[idx];
                }
            }
#pragma unroll
            for (int n2 = 0; n2 < 4; ++n2) {
                int ot = nq * 4 + n2;
                uint2 bb = *(const uint2*)&WBH[((ot * 8 + kg) * 32 + lane) * 2];
                Bh[n2][0] = bb.x; Bh[n2][1] = bb.y;
            }
#pragma unroll
            for (int m2 = 0; m2 < 2; ++m2)
#pragma unroll
                for (int n2 = 0; n2 < 4; ++n2) {
                    mma16816h(acc[m2][n2], Ah[m2], Bh[n2]);
                    if (p == 0) mma16816h(acc[m2][n2], Al[m2], Bh[n2]);
                }
        }

        if (p == 2) __syncthreads();   // all warps done reading A-frags -> V may overlay

#pragma unroll
        for (int m2 = 0; m2 < 2; ++m2)
#pragma unroll
            for (int n2 = 0; n2 < 4; ++n2) {
                int TT = mt * 2 + m2, hh = nq * 4 + n2;
                int o0 = hh * 8 + (tig << 1);
                float b0 = bsrc[p][o0], b1 = bsrc[p][o0 + 1];
                float v0 = acc[m2][n2][0] + b0, v1 = acc[m2][n2][1] + b1;
                float v2 = acc[m2][n2][2] + b0, v3 = acc[m2][n2][3] + b1;
                if (p == 0) {
                    const float SC = 0.5101344248f;    // 1/sqrt(8) * log2(e)
                    v0 *= SC; v1 *= SC; v2 *= SC; v3 *= SC;
                    u32 hi, lo;
                    split2h(v0, v1, hi, lo);
                    *(uint2*)&QHL[(((hh * 8 + TT) * 2 + 0) * 32 + lane) * 2] = make_uint2(hi, lo);
                    split2h(v2, v3, hi, lo);
                    *(uint2*)&QHL[(((hh * 8 + TT) * 2 + 1) * 32 + lane) * 2] = make_uint2(hi, lo);
                } else if (p == 1) {
                    BKH[(hh * 16 + TT * 2) * 32 + lane]     = pack_h2(v0, v1);
                    BKH[(hh * 16 + TT * 2 + 1) * 32 + lane] = pack_h2(v2, v3);
                } else {
                    // V single fp16, transpose scatter [validated offsets]
                    char* bh = smc + SM_VBH + hh * 2048 + TT * 256;
                    int d0 = tig << 1, d1 = d0 + 1;
                    int wo0 = d0 * 16 + ((gid >> 1) << 2) + ((gid & 1) << 1);
                    int wo1 = d1 * 16 + ((gid >> 1) << 2) + ((gid & 1) << 1);
                    vstoreh(bh, wo0, v0);
                    vstoreh(bh, wo1, v1);
                    vstoreh(bh, 128 + wo0, v2);
                    vstoreh(bh, 128 + wo1, v3);
                }
            }
    }
    __syncthreads();    // Q + K + V smem visible

    // ---- attention: warp w = head h, all mi 0..7; QK as one packed k16 ----
    float oa[8][4];
    float l0[8], l1[8];
    {
        const int h = w;
        const bool m0 = (2 * tig) <= gid;
        const bool m1 = (2 * tig + 1) <= gid;

        u32 qp[8][4];                       // {hi0, hi1, lo0, lo1} per mi
#pragma unroll
        for (int mi = 0; mi < 8; ++mi) {
            uint2 q0 = *(const uint2*)&QHL[(((h * 8 + mi) * 2 + 0) * 32 + lane) * 2];
            uint2 q1 = *(const uint2*)&QHL[(((h * 8 + mi) * 2 + 1) * 32 + lane) * 2];
            qp[mi][0] = q0.x; qp[mi][1] = q1.x;
            qp[mi][2] = q0.y; qp[mi][3] = q1.y;
        }
#pragma unroll
        for (int mi = 0; mi < 8; ++mi) {
            oa[mi][0] = oa[mi][1] = oa[mi][2] = oa[mi][3] = 0.f;
            l0[mi] = l1[mi] = 0.f;
        }

#pragma unroll
        for (int kg = 0; kg < 8; ++kg) {
            u32 kh0 = BKH[(h * 16 + 2 * kg) * 32 + lane];
            u32 kh1 = BKH[(h * 16 + 2 * kg + 1) * 32 + lane];
            u32 kb0[2] = {kh0, kh0};
            u32 kb1[2] = {kh1, kh1};
            u32 vh[2];
            vh[0] = VBH[((h * 8 + kg) * 2 + 0) * 32 + lane];
            vh[1] = VBH[((h * 8 + kg) * 2 + 1) * 32 + lane];

#pragma unroll
            for (int mi = 0; mi < 8; ++mi) {
                if (mi < kg) continue;               // compile-time prune
                bool diag = (mi == kg);

                float s0[4] = {0.f, 0.f, 0.f, 0.f};
                float s1[4] = {0.f, 0.f, 0.f, 0.f};
                // S = [Qhi,Qlo] (k16) x [K;K]  == Qhi*K + Qlo*K
                mma16816h(s0, qp[mi], kb0);
                mma16816h(s1, qp[mi], kb1);

                float e00 = ex2f(s0[0]), e01 = ex2f(s0[1]);
                float e02 = ex2f(s0[2]), e03 = ex2f(s0[3]);
                float e10 = ex2f(s1[0]), e11 = ex2f(s1[1]);
                float e12 = ex2f(s1[2]), e13 = ex2f(s1[3]);
                if (diag) {
                    e00 = m0 ? e00 : 0.f; e01 = m1 ? e01 : 0.f;
                    e10 = 0.f;            e11 = 0.f;
                    e12 = m0 ? e12 : 0.f; e13 = m1 ? e13 : 0.f;
                }
                l0[mi] += (e00 + e01) + (e10 + e11);
                l1[mi] += (e02 + e03) + (e12 + e13);

                // P single fp16 (no lo split)
                u32 ph[4];
                ph[0] = pack_h2(e00, e01);
                ph[1] = pack_h2(e02, e03);
                ph[2] = pack_h2(e10, e11);
                ph[3] = pack_h2(e12, e13);

                mma16816h(oa[mi], ph, vh);
            }
        }
    }
    __syncthreads();          // all warps done reading K/V regions

    // ---- normalize + write AO frags (single fp16, overlay A-lo region) ----
    {
        const int h = w;
#pragma unroll
        for (int mi = 0; mi < 8; ++mi) {
            float L0 = l0[mi], L1 = l1[mi];
            L0 += __shfl_xor_sync(0xFFFFFFFFu, L0, 1);
            L0 += __shfl_xor_sync(0xFFFFFFFFu, L0, 2);
            L1 += __shfl_xor_sync(0xFFFFFFFFu, L1, 1);
            L1 += __shfl_xor_sync(0xFFFFFFFFu, L1, 2);
            float inv0 = __fdividef(1.f, L0), inv1 = __fdividef(1.f, L1);
            float r0 = oa[mi][0] * inv0, r1 = oa[mi][1] * inv0;
            float r2 = oa[mi][2] * inv1, r3 = oa[mi][3] * inv1;

            int kga = h >> 1, regb = (h & 1) << 1;
            int X0 = (mi * 2) & 3, X1 = (mi * 2 + 1) & 3;
            int base = (mi * 4 + kga) * 4;
            AOH[(base + regb) * 32 + (lane ^ X0)]     = pack_h2(r0, r1);
            AOH[(base + regb + 1) * 32 + (lane ^ X1)] = pack_h2(r2, r3);
        }
    }
    __syncthreads();

    // ---- out projection (A single x Wo single) + bias + ReLU -> global ----
    {
        float acc[2][4][4];
#pragma unroll
        for (int m2 = 0; m2 < 2; ++m2)
#pragma unroll
            for (int n2 = 0; n2 < 4; ++n2)
#pragma unroll
                for (int j = 0; j < 4; ++j) acc[m2][n2][j] = 0.f;

#pragma unroll
        for (int kg = 0; kg < 4; ++kg) {
            u32 Ah[2][4], Bh[4][2];
#pragma unroll
            for (int m2 = 0; m2 < 2; ++m2) {
                int tt = mt * 2 + m2;
#pragma unroll
                for (int r = 0; r < 4; ++r) {
                    int X = (tt * 2 + (r & 1)) & 3;
                    int idx = ((tt * 4 + kg) * 4 + r) * 32 + (lane ^ X);
                    Ah[m2][r] = AOH[idx];
                }
            }
#pragma unroll
            for (int n2 = 0; n2 < 4; ++n2) {
                int ot = nq * 4 + n2;
                uint2 bb = *(const uint2*)&gWOH[((ot * 4 + kg) * 32 + lane) * 2];
                Bh[n2][0] = bb.x; Bh[n2][1] = bb.y;
            }
#pragma unroll
            for (int m2 = 0; m2 < 2; ++m2)
#pragma unroll
                for (int n2 = 0; n2 < 4; ++n2)
                    mma16816h(acc[m2][n2], Ah[m2], Bh[n2]);
        }

#pragma unroll
        for (int m2 = 0; m2 < 2; ++m2)
#pragma unroll
            for (int n2 = 0; n2 < 4; ++n2) {
                int t0 = ((mt * 2 + m2) << 4) + gid;
                int o0 = ((nq * 4 + n2) << 3) + (tig << 1);
                float b0 = bo[o0], b1 = bo[o0 + 1];
                long base0 = ((long)(b * 64 + o0) * V_ + v) * T_;
                long base1 = base0 + (long)V_ * T_;
                out[base0 + t0]     = fmaxf(acc[m2][n2][0] + b0, 0.f);
                out[base1 + t0]     = fmaxf(acc[m2][n2][1] + b1, 0.f);
                out[base0 + t0 + 8] = fmaxf(acc[m2][n2][2] + b0, 0.f);
                out[base1 + t0 + 8] = fmaxf(acc[m2][n2][3] + b1, 0.f);
            }
    }
}

// ---------------------------------------------------------------------------
extern "C" void kernel_launch(void* const* d_in, const int* in_sizes, int n_in,
                              void* d_out, int out_size)
{
    (void)in_sizes; (void)n_in; (void)out_size;
    const float* x  = (const float*)d_in[0];
    const float* te = (const float*)d_in[1];
    const float* Wq = (const float*)d_in[2];
    const float* bq = (const float*)d_in[3];
    const float* Wk = (const float*)d_in[4];
    const float* bk = (const float*)d_in[5];
    const float* Wv = (const float*)d_in[6];
    const float* bv = (const float*)d_in[7];
    const float* Wo = (const float*)d_in[8];
    const float* bo = (const float*)d_in[9];
    float* out = (float*)d_out;

    cudaFuncSetAttribute(tatt_fused, cudaFuncAttributeMaxDynamicSharedMemorySize, SMEM_TOTAL);

    prep_w<<<4, 1024>>>(Wq, Wk, Wv, Wo);
    tatt_fused<<<NBLK, 256, SMEM_TOTAL>>>(x, te, bq, bk, bv, bo, out);
}

// round 17
// speedup vs baseline: 1.3140x; 1.1688x over previous
#include <cuda_runtime.h>
#include <cuda_fp16.h>
#include <cstdint>

typedef unsigned long long u64;
typedef unsigned int       u32;

#define B_   8
#define V_   200
#define T_   128
#define NBLK (B_ * V_)          // 1600

// ---- pre-fragmented weights (written once by prep_w); reg-paired layout ----
__device__ __align__(16) u32 gWBH[3 * 4096];
__device__ __align__(16) u32 gWOH[2048];

// ---- fused-kernel smem (bytes), 112KB -> 2 CTAs/SM ----
#define SM_AFH  0
#define SM_AFL  32768
#define SM_VBH  0
#define SM_AOH  32768
#define SM_QHL  65536
#define SM_BKH  98304
#define SMEM_TOTAL 114688

// ---- helpers (fp16) ----
__device__ __forceinline__ u32 pack_h2(float a, float b) {
    __half2 h = __floats2half2_rn(a, b);
    return *(u32*)&h;
}
__device__ __forceinline__ void split2h(float a, float b, u32& hi, u32& lo) {
    hi = pack_h2(a, b);
    float ra = __half2float(__ushort_as_half((unsigned short)(hi & 0xFFFFu)));
    float rb = __half2float(__ushort_as_half((unsigned short)(hi >> 16)));
    lo = pack_h2(a - ra, b - rb);
}
__device__ __forceinline__ u32 h2ex2(u32 x) {
    u32 y; asm("ex2.approx.f16x2 %0, %1;" : "=r"(y) : "r"(x)); return y;
}
__device__ __forceinline__ u32 hadd2u(u32 a, u32 b) {
    u32 c; asm("add.rn.f16x2 %0, %1, %2;" : "=r"(c) : "r"(a), "r"(b)); return c;
}
__device__ __forceinline__ float2 h2f2(u32 a) {
    __half2 h = *(__half2*)&a;
    return __half22float2(h);
}
__device__ __forceinline__ void mma16816h(float* c, const u32* a, const u32* b) {
    asm volatile(
        "mma.sync.aligned.m16n8k16.row.col.f32.f16.f16.f32 "
        "{%0,%1,%2,%3}, {%4,%5,%6,%7}, {%8,%9}, {%0,%1,%2,%3};"
        : "+f"(c[0]), "+f"(c[1]), "+f"(c[2]), "+f"(c[3])
        : "r"(a[0]), "r"(a[1]), "r"(a[2]), "r"(a[3]), "r"(b[0]), "r"(b[1]));
}
__device__ __forceinline__ void vstoreh(char* bh, int off, float v) {
    *(__half*)(bh + off) = __float2half_rn(v);
}

extern __shared__ char smc[];

// ===========================================================================
// Kernel 0: pre-fragment weights (reg-paired layout, LDG.64 consumers)
// ===========================================================================
__global__ void prep_w(const float* __restrict__ Wq, const float* __restrict__ Wk,
                       const float* __restrict__ Wv, const float* __restrict__ Wo)
{
    const int p = blockIdx.x, tid = threadIdx.x;
    if (p < 3) {
        const float* W = (p == 0) ? Wq : (p == 1 ? Wk : Wv);
        for (int i = tid; i < 4096; i += 1024) {
            int o = i >> 6, cp = i & 63;
            float2 g = *(const float2*)(W + o * 128 + (cp << 1));
            int ot = o >> 3, kg = cp >> 3;
            int reg = (cp >> 2) & 1;
            int lane_f = ((o & 7) << 2) + (cp & 3);
            int idx = ((ot * 8 + kg) * 32 + lane_f) * 2 + reg;
            gWBH[p * 4096 + idx] = pack_h2(g.x, g.y);
        }
    } else {
        for (int i = tid; i < 2048; i += 1024) {
            int o = i >> 5, cp = i & 31;
            float2 g = *(const float2*)(Wo + (o << 6) + (cp << 1));
            int ot = o >> 3, kg = cp >> 3;
            int reg = (cp >> 2) & 1;
            int lane_f = ((o & 7) << 2) + (cp & 3);
            int idx = ((ot * 4 + kg) * 32 + lane_f) * 2 + reg;
            gWOH[idx] = pack_h2(g.x, g.y);
        }
    }
}

// ===========================================================================
// Fused kernel: concat + QKV proj + causal attention + out-proj + ReLU
// 256 threads, 2 CTAs/SM (112KB smem).
// ===========================================================================
__global__ __launch_bounds__(256, 2) void tatt_fused(
    const float* __restrict__ x,  const float* __restrict__ tem,
    const float* __restrict__ bq, const float* __restrict__ bk,
    const float* __restrict__ bv, const float* __restrict__ bo,
    float* __restrict__ out)
{
    u32* AFH = (u32*)(smc + SM_AFH);
    u32* AFL = (u32*)(smc + SM_AFL);
    u32* QHL = (u32*)(smc + SM_QHL);
    u32* BKH = (u32*)(smc + SM_BKH);
    u32* VBH = (u32*)(smc + SM_VBH);
    u32* AOH = (u32*)(smc + SM_AOH);

    const int tid = threadIdx.x, lane = tid & 31, w = tid >> 5;
    const int blk = blockIdx.x, b = blk / V_, v = blk % V_;
    const int gid = lane >> 2, tig = lane & 3;

    // ---- stage concat input as A-fragments; float4 global loads ----
    for (int i = tid; i < 2048; i += 256) {
        int cp = i >> 5;
        int t0 = (i & 31) << 2;
        int c0 = cp << 1;
        const float* src = (c0 < 64) ? x : tem;
        const float* pb = src + ((long)((b << 6) + (c0 & 63)) * V_ + v) * T_ + t0;
        float4 ga = *(const float4*)pb;
        float4 gb = *(const float4*)(pb + (long)V_ * T_);
        float a4[4] = {ga.x, ga.y, ga.z, ga.w};
        float b4[4] = {gb.x, gb.y, gb.z, gb.w};
        int kg = cp >> 3;
#pragma unroll
        for (int k = 0; k < 4; ++k) {
            int t = t0 + k;
            int tt = t >> 4, tin = t & 15;
            int lane_f = ((tin & 7) << 2) + (cp & 3);
            int reg = (tin >> 3) + (((cp >> 2) & 1) << 1);
            int X = (t >> 3) & 3;
            int idx = (((tt << 3) + kg) * 4 + reg) * 32 + (lane_f ^ X);
            split2h(a4[k], b4[k], AFH[idx], AFL[idx]);
        }
    }
    __syncthreads();

    const int mt = w >> 1, nq = w & 1;        // 4 x 2 warp grid

    // ---- Q projection (2-term: A split x W single) ----
    {
        const u32* WBH = gWBH;
        float acc[2][4][4];
#pragma unroll
        for (int m2 = 0; m2 < 2; ++m2)
#pragma unroll
            for (int n2 = 0; n2 < 4; ++n2)
#pragma unroll
                for (int j = 0; j < 4; ++j) acc[m2][n2][j] = 0.f;

#pragma unroll
        for (int kg = 0; kg < 8; ++kg) {
            u32 Ah[2][4], Al[2][4], Bh[4][2];
#pragma unroll
            for (int m2 = 0; m2 < 2; ++m2) {
                int tt = mt * 2 + m2;
#pragma unroll
                for (int r = 0; r < 4; ++r) {
                    int X = (tt * 2 + (r & 1)) & 3;
                    int idx = ((tt * 8 + kg) * 4 + r) * 32 + (lane ^ X);
                    Ah[m2][r] = AFH[idx];
                    Al[m2][r] = AFL[idx];
                }
            }
#pragma unroll
            for (int n2 = 0; n2 < 4; ++n2) {
                int ot = nq * 4 + n2;
                uint2 bb = *(const uint2*)&WBH[((ot * 8 + kg) * 32 + lane) * 2];
                Bh[n2][0] = bb.x; Bh[n2][1] = bb.y;
            }
#pragma unroll
            for (int m2 = 0; m2 < 2; ++m2)
#pragma unroll
                for (int n2 = 0; n2 < 4; ++n2) {
                    mma16816h(acc[m2][n2], Ah[m2], Bh[n2]);
                    mma16816h(acc[m2][n2], Al[m2], Bh[n2]);
                }
        }

#pragma unroll
        for (int m2 = 0; m2 < 2; ++m2)
#pragma unroll
            for (int n2 = 0; n2 < 4; ++n2) {
                int TT = mt * 2 + m2, hh = nq * 4 + n2;
                int o0 = hh * 8 + (tig << 1);
                const float SC = 0.5101344248f;    // 1/sqrt(8) * log2(e)
                float v0 = (acc[m2][n2][0] + bq[o0])     * SC;
                float v1 = (acc[m2][n2][1] + bq[o0 + 1]) * SC;
                float v2 = (acc[m2][n2][2] + bq[o0])     * SC;
                float v3 = (acc[m2][n2][3] + bq[o0 + 1]) * SC;
                u32 hi, lo;
                split2h(v0, v1, hi, lo);
                *(uint2*)&QHL[(((hh * 8 + TT) * 2 + 0) * 32 + lane) * 2] = make_uint2(hi, lo);
                split2h(v2, v3, hi, lo);
                *(uint2*)&QHL[(((hh * 8 + TT) * 2 + 1) * 32 + lane) * 2] = make_uint2(hi, lo);
            }
    }

    // ---- K and V projections (1-term) ----
#pragma unroll 1
    for (int p = 1; p < 3; ++p) {
        const u32* WBH = gWBH + p * 4096;
        const float* bb_ = (p == 1) ? bk : bv;

        float acc[2][4][4];
#pragma unroll
        for (int m2 = 0; m2 < 2; ++m2)
#pragma unroll
            for (int n2 = 0; n2 < 4; ++n2)
#pragma unroll
                for (int j = 0; j < 4; ++j) acc[m2][n2][j] = 0.f;

#pragma unroll
        for (int kg = 0; kg < 8; ++kg) {
            u32 Ah[2][4], Bh[4][2];
#pragma unroll
            for (int m2 = 0; m2 < 2; ++m2) {
                int tt = mt * 2 + m2;
#pragma unroll
                for (int r = 0; r < 4; ++r) {
                    int X = (tt * 2 + (r & 1)) & 3;
                    int idx = ((tt * 8 + kg) * 4 + r) * 32 + (lane ^ X);
                    Ah[m2][r] = AFH[idx];
                }
            }
#pragma unroll
            for (int n2 = 0; n2 < 4; ++n2) {
                int ot = nq * 4 + n2;
                uint2 bb = *(const uint2*)&WBH[((ot * 8 + kg) * 32 + lane) * 2];
                Bh[n2][0] = bb.x; Bh[n2][1] = bb.y;
            }
#pragma unroll
            for (int m2 = 0; m2 < 2; ++m2)
#pragma unroll
                for (int n2 = 0; n2 < 4; ++n2)
                    mma16816h(acc[m2][n2], Ah[m2], Bh[n2]);
        }

        if (p == 2) __syncthreads();   // all warps done reading A-frags -> V may overlay

#pragma unroll
        for (int m2 = 0; m2 < 2; ++m2)
#pragma unroll
            for (int n2 = 0; n2 < 4; ++n2) {
                int TT = mt * 2 + m2, hh = nq * 4 + n2;
                int o0 = hh * 8 + (tig << 1);
                float b0 = bb_[o0], b1 = bb_[o0 + 1];
                float v0 = acc[m2][n2][0] + b0, v1 = acc[m2][n2][1] + b1;
                float v2 = acc[m2][n2][2] + b0, v3 = acc[m2][n2][3] + b1;
                if (p == 1) {
                    // K pairs interleaved: one STS.64
                    *(uint2*)&BKH[((hh * 8 + TT) * 32 + lane) * 2] =
                        make_uint2(pack_h2(v0, v1), pack_h2(v2, v3));
                } else {
                    // V single fp16, transpose scatter [validated offsets]
                    char* bh = smc + SM_VBH + hh * 2048 + TT * 256;
                    int d0 = tig << 1, d1 = d0 + 1;
                    int wo0 = d0 * 16 + ((gid >> 1) << 2) + ((gid & 1) << 1);
                    int wo1 = d1 * 16 + ((gid >> 1) << 2) + ((gid & 1) << 1);
                    vstoreh(bh, wo0, v0);
                    vstoreh(bh, wo1, v1);
                    vstoreh(bh, 128 + wo0, v2);
                    vstoreh(bh, 128 + wo1, v3);
                }
            }
    }
    __syncthreads();    // Q + K + V smem visible

    // ---- attention: warp w = head h, all mi 0..7; fp16x2 exp path ----
    float oa[8][4];
    float l0[8], l1[8];
    {
        const int h = w;
        const bool m0 = (2 * tig) <= gid;
        const bool m1 = (2 * tig + 1) <= gid;
        const u32 mask01 = (m0 ? 0xFFFFu : 0u) | (m1 ? 0xFFFF0000u : 0u);

        u32 qp[8][4];                       // {hi0, hi1, lo0, lo1} per mi
#pragma unroll
        for (int mi = 0; mi < 8; ++mi) {
            uint2 q0 = *(const uint2*)&QHL[(((h * 8 + mi) * 2 + 0) * 32 + lane) * 2];
            uint2 q1 = *(const uint2*)&QHL[(((h * 8 + mi) * 2 + 1) * 32 + lane) * 2];
            qp[mi][0] = q0.x; qp[mi][1] = q1.x;
            qp[mi][2] = q0.y; qp[mi][3] = q1.y;
        }
#pragma unroll
        for (int mi = 0; mi < 8; ++mi) {
            oa[mi][0] = oa[mi][1] = oa[mi][2] = oa[mi][3] = 0.f;
            l0[mi] = l1[mi] = 0.f;
        }

#pragma unroll
        for (int kg = 0; kg < 8; ++kg) {
            uint2 kk = *(const uint2*)&BKH[((h * 8 + kg) * 32 + lane) * 2];
            u32 kb0[2] = {kk.x, kk.x};
            u32 kb1[2] = {kk.y, kk.y};
            u32 vh[2];
            vh[0] = VBH[((h * 8 + kg) * 2 + 0) * 32 + lane];
            vh[1] = VBH[((h * 8 + kg) * 2 + 1) * 32 + lane];

#pragma unroll
            for (int mi = 0; mi < 8; ++mi) {
                if (mi < kg) continue;               // compile-time prune
                bool diag = (mi == kg);

                float s0[4] = {0.f, 0.f, 0.f, 0.f};
                float s1[4] = {0.f, 0.f, 0.f, 0.f};
                mma16816h(s0, qp[mi], kb0);
                mma16816h(s1, qp[mi], kb1);

                // pack scores to f16x2, exponentiate in f16x2 (P frags direct)
                u32 ph[4];
                ph[0] = h2ex2(pack_h2(s0[0], s0[1]));   // {e00,e01} row gid
                ph[1] = h2ex2(pack_h2(s0[2], s0[3]));   // {e02,e03} row gid+8
                ph[2] = h2ex2(pack_h2(s1[0], s1[1]));   // {e10,e11} row gid
                ph[3] = h2ex2(pack_h2(s1[2], s1[3]));   // {e12,e13} row gid+8
                if (diag) {
                    ph[0] &= mask01;
                    ph[2] = 0u;
                    ph[3] &= mask01;
                }
                // l: row sums via f16x2 adds, accumulate fp32
                u32 t01 = hadd2u(ph[0], ph[2]);
                u32 t23 = hadd2u(ph[1], ph[3]);
                float2 f01 = h2f2(t01);
                float2 f23 = h2f2(t23);
                l0[mi] += f01.x + f01.y;
                l1[mi] += f23.x + f23.y;

                mma16816h(oa[mi], ph, vh);
            }
        }
    }
    __syncthreads();          // all warps done reading K/V regions

    // ---- normalize + write AO frags (single fp16, overlay A-lo region) ----
    {
        const int h = w;
#pragma unroll
        for (int mi = 0; mi < 8; ++mi) {
            float L0 = l0[mi], L1 = l1[mi];
            L0 += __shfl_xor_sync(0xFFFFFFFFu, L0, 1);
            L0 += __shfl_xor_sync(0xFFFFFFFFu, L0, 2);
            L1 += __shfl_xor_sync(0xFFFFFFFFu, L1, 1);
            L1 += __shfl_xor_sync(0xFFFFFFFFu, L1, 2);
            float inv0 = __fdividef(1.f, L0), inv1 = __fdividef(1.f, L1);
            float r0 = oa[mi][0] * inv0, r1 = oa[mi][1] * inv0;
            float r2 = oa[mi][2] * inv1, r3 = oa[mi][3] * inv1;

            int kga = h >> 1, regb = (h & 1) << 1;
            int X0 = (mi * 2) & 3, X1 = (mi * 2 + 1) & 3;
            int base = (mi * 4 + kga) * 4;
            AOH[(base + regb) * 32 + (lane ^ X0)]     = pack_h2(r0, r1);
            AOH[(base + regb + 1) * 32 + (lane ^ X1)] = pack_h2(r2, r3);
        }
    }
    __syncthreads();

    // ---- out projection (A single x Wo single) + bias + ReLU -> global ----
    {
        float acc[2][4][4];
#pragma unroll
        for (int m2 = 0; m2 < 2; ++m2)
#pragma unroll
            for (int n2 = 0; n2 < 4; ++n2)
#pragma unroll
                for (int j = 0; j < 4; ++j) acc[m2][n2][j] = 0.f;

#pragma unroll
        for (int kg = 0; kg < 4; ++kg) {
            u32 Ah[2][4], Bh[4][2];
#pragma unroll
            for (int m2 = 0; m2 < 2; ++m2) {
                int tt = mt * 2 + m2;
#pragma unroll
                for (int r = 0; r < 4; ++r) {
                    int X = (tt * 2 + (r & 1)) & 3;
                    int idx = ((tt * 4 + kg) * 4 + r) * 32 + (lane ^ X);
                    Ah[m2][r] = AOH[idx];
                }
            }
#pragma unroll
            for (int n2 = 0; n2 < 4; ++n2) {
                int ot = nq * 4 + n2;
                uint2 bb = *(const uint2*)&gWOH[((ot * 4 + kg) * 32 + lane) * 2];
                Bh[n2][0] = bb.x; Bh[n2][1] = bb.y;
            }
#pragma unroll
            for (int m2 = 0; m2 < 2; ++m2)
#pragma unroll
                for (int n2 = 0; n2 < 4; ++n2)
                    mma16816h(acc[m2][n2], Ah[m2], Bh[n2]);
        }

#pragma unroll
        for (int m2 = 0; m2 < 2; ++m2)
#pragma unroll
            for (int n2 = 0; n2 < 4; ++n2) {
                int t0 = ((mt * 2 + m2) << 4) + gid;
                int o0 = ((nq * 4 + n2) << 3) + (tig << 1);
                float b0 = bo[o0], b1 = bo[o0 + 1];
                long base0 = ((long)(b * 64 + o0) * V_ + v) * T_;
                long base1 = base0 + (long)V_ * T_;
                out[base0 + t0]     = fmaxf(acc[m2][n2][0] + b0, 0.f);
                out[base1 + t0]     = fmaxf(acc[m2][n2][1] + b1, 0.f);
                out[base0 + t0 + 8] = fmaxf(acc[m2][n2][2] + b0, 0.f);
                out[base1 + t0 + 8] = fmaxf(acc[m2][n2][3] + b1, 0.f);
            }
    }
}

// ---------------------------------------------------------------------------
extern "C" void kernel_launch(void* const* d_in, const int* in_sizes, int n_in,
                              void* d_out, int out_size)
{
    (void)in_sizes; (void)n_in; (void)out_size;
    const float* x  = (const float*)d_in[0];
    const float* te = (const float*)d_in[1];
    const float* Wq = (const float*)d_in[2];
    const float* bq = (const float*)d_in[3];
    const float* Wk = (const float*)d_in[4];
    const float* bk = (const float*)d_in[5];
    const float* Wv = (const float*)d_in[6];
    const float* bv = (const float*)d_in[7];
    const float* Wo = (const float*)d_in[8];
    const float* bo = (const float*)d_in[9];
    float* out = (float*)d_out;

    cudaFuncSetAttribute(tatt_fused, cudaFuncAttributeMaxDynamicSharedMemorySize, SMEM_TOTAL);

    prep_w<<<4, 1024>>>(Wq, Wk, Wv, Wo);
    tatt_fused<<<NBLK, 256, SMEM_TOTAL>>>(x, te, bq, bk, bv, bo, out);
}